// round 13
// baseline (speedup 1.0000x reference)
#include <cuda_runtime.h>
#include <cuda_bf16.h>
#include <cstdint>

// SpatialAttentionLayer_23381801959766  — FINAL
//
// Reference math:
//   attn = softmax(fourier_maps(sensor_locs) @ W, axis=-1)   # rows sum to 1
//   out  = einsum('si,sjk->sjk', attn, X)                    # i summed out
//        = X * (row-sum of softmax) = X  (rel_err ~6e-8, fp32 ULP only)
//
// The layer is algebraically the identity on X -> 142.6 MB HBM streaming
// copy (285 MB nominal traffic). 12 rounds established a ~6.05 TB/s plateau
// (37.3-39.0us kernel) that is invariant under: vector width (128/256-bit),
// per-thread MLP (4/8), the full L2 eviction-policy grid on both read and
// write streams, partitioned residency pinning, and grid/wave structure.
// That plateau is the HBM read/write-turnaround floor on this part.
//
// Final config (best measured: 37.3us kernel, 45.57us total):
//   - 8704 CTAs x 256 thr, 64 B/thread, exact cover (no tail at this shape)
//   - v8 256-bit .cs front-batched loads (MLP=2x32B, evict-first reads)
//   - first 100 MB of out stored L2::evict_last, tail .cs (write-side
//     residency attempt; harmless, tied-best measured)

static constexpr int THREADS = 256;
static constexpr size_t FLOATS_PER_BLOCK = (size_t)THREADS * 16;  // 16 KB
static constexpr unsigned PIN_BLOCKS = 6400;  // 100 MB boundary of out

__device__ __forceinline__ void ldg256_cs(const float* __restrict__ p, float* v) {
    asm volatile(
        "ld.global.cs.v8.f32 {%0,%1,%2,%3,%4,%5,%6,%7}, [%8];"
        : "=f"(v[0]), "=f"(v[1]), "=f"(v[2]), "=f"(v[3]),
          "=f"(v[4]), "=f"(v[5]), "=f"(v[6]), "=f"(v[7])
        : "l"(p));
}

__device__ __forceinline__ void stg256_el(float* __restrict__ p, const float* v) {
    asm volatile(
        "st.global.L2::evict_last.v8.f32 [%0], {%1,%2,%3,%4,%5,%6,%7,%8};"
        :: "l"(p),
           "f"(v[0]), "f"(v[1]), "f"(v[2]), "f"(v[3]),
           "f"(v[4]), "f"(v[5]), "f"(v[6]), "f"(v[7])
        : "memory");
}

__device__ __forceinline__ void stg256_cs(float* __restrict__ p, const float* v) {
    asm volatile(
        "st.global.cs.v8.f32 [%0], {%1,%2,%3,%4,%5,%6,%7,%8};"
        :: "l"(p),
           "f"(v[0]), "f"(v[1]), "f"(v[2]), "f"(v[3]),
           "f"(v[4]), "f"(v[5]), "f"(v[6]), "f"(v[7])
        : "memory");
}

__global__ __launch_bounds__(THREADS)
void stream_copy_kernel(const float* __restrict__ in, float* __restrict__ out) {
    size_t base = (size_t)blockIdx.x * FLOATS_PER_BLOCK + (size_t)threadIdx.x * 8;
    size_t off1 = (size_t)THREADS * 8;

    float v0[8], v1[8];
    ldg256_cs(in + base, v0);          // front-batched streaming reads
    ldg256_cs(in + base + off1, v1);

    if (blockIdx.x < PIN_BLOCKS) {
        stg256_el(out + base, v0);     // write-residency region
        stg256_el(out + base + off1, v1);
    } else {
        stg256_cs(out + base, v0);     // streaming write tail
        stg256_cs(out + base + off1, v1);
    }
}

// Tail kernel for any remainder (unused at this exact shape; kept for
// correctness on arbitrary out_size).
__global__ void stream_copy_tail(const float* __restrict__ in,
                                 float* __restrict__ out,
                                 size_t start, size_t n) {
    size_t i = start + blockIdx.x * (size_t)blockDim.x + threadIdx.x;
    if (i < n) out[i] = __ldcs(in + i);
}

extern "C" void kernel_launch(void* const* d_in, const int* in_sizes, int n_in,
                              void* d_out, int out_size) {
    const float* X = (const float*)d_in[0];
    float* out = (float*)d_out;

    size_t n = (size_t)out_size;                 // 35,651,584 floats
    size_t full_blocks = n / FLOATS_PER_BLOCK;   // 8704 exact here

    if (full_blocks > 0) {
        stream_copy_kernel<<<(unsigned)full_blocks, THREADS>>>(X, out);
    }
    size_t done = full_blocks * FLOATS_PER_BLOCK;
    if (done < n) {
        size_t rem = n - done;
        unsigned tb = (unsigned)((rem + 255) / 256);
        stream_copy_tail<<<tb, 256>>>(X, out, done, n);
    }
}

// round 14
// speedup vs baseline: 1.0337x; 1.0337x over previous
#include <cuda_runtime.h>
#include <cuda_bf16.h>
#include <cstdint>

// SpatialAttentionLayer_23381801959766  — FINAL (unchanged from R12/R13)
//
// Reference math:
//   attn = softmax(fourier_maps(sensor_locs) @ W, axis=-1)   # rows sum to 1
//   out  = einsum('si,sjk->sjk', attn, X)                    # i summed out
//        = X * (row-sum of softmax) = X  (rel_err ~6e-8, fp32 ULP only)
//
// The layer is algebraically the identity on X -> 142.6 MB HBM streaming
// copy. 13 rounds established a ~6.0-6.1 TB/s plateau (36.7-39.0us kernel;
// 76% of 8 TB/s spec = the HBM read/write-turnaround floor on this part),
// invariant under: vector width (128/256-bit), per-thread MLP (4/8), the
// full L2 eviction-policy grid on both streams, partitioned residency
// pinning (read-side and write-side), and grid/wave structure (persistent
// grids regress: the CTA scheduler's natural pipelining of front-batched
// load groups beats a loop-carried grid-stride body).
//
// Best measured with this exact binary: kernel 36.7us, dur_us 45.57
// (remaining ~8us of dur_us is fixed harness/graph overhead).
//
// Config:
//   - 8704 CTAs x 256 thr, 64 B/thread, exact cover at this shape
//   - v8 256-bit .cs front-batched loads (streaming, evict-first)
//   - first 100 MB of out: st L2::evict_last (v8 form required by ptxas);
//     tail: st .cs

static constexpr int THREADS = 256;
static constexpr size_t FLOATS_PER_BLOCK = (size_t)THREADS * 16;  // 16 KB
static constexpr unsigned PIN_BLOCKS = 6400;  // 100 MB boundary of out

__device__ __forceinline__ void ldg256_cs(const float* __restrict__ p, float* v) {
    asm volatile(
        "ld.global.cs.v8.f32 {%0,%1,%2,%3,%4,%5,%6,%7}, [%8];"
        : "=f"(v[0]), "=f"(v[1]), "=f"(v[2]), "=f"(v[3]),
          "=f"(v[4]), "=f"(v[5]), "=f"(v[6]), "=f"(v[7])
        : "l"(p));
}

__device__ __forceinline__ void stg256_el(float* __restrict__ p, const float* v) {
    asm volatile(
        "st.global.L2::evict_last.v8.f32 [%0], {%1,%2,%3,%4,%5,%6,%7,%8};"
        :: "l"(p),
           "f"(v[0]), "f"(v[1]), "f"(v[2]), "f"(v[3]),
           "f"(v[4]), "f"(v[5]), "f"(v[6]), "f"(v[7])
        : "memory");
}

__device__ __forceinline__ void stg256_cs(float* __restrict__ p, const float* v) {
    asm volatile(
        "st.global.cs.v8.f32 [%0], {%1,%2,%3,%4,%5,%6,%7,%8};"
        :: "l"(p),
           "f"(v[0]), "f"(v[1]), "f"(v[2]), "f"(v[3]),
           "f"(v[4]), "f"(v[5]), "f"(v[6]), "f"(v[7])
        : "memory");
}

__global__ __launch_bounds__(THREADS)
void stream_copy_kernel(const float* __restrict__ in, float* __restrict__ out) {
    size_t base = (size_t)blockIdx.x * FLOATS_PER_BLOCK + (size_t)threadIdx.x * 8;
    size_t off1 = (size_t)THREADS * 8;

    float v0[8], v1[8];
    ldg256_cs(in + base, v0);          // front-batched streaming reads
    ldg256_cs(in + base + off1, v1);

    if (blockIdx.x < PIN_BLOCKS) {
        stg256_el(out + base, v0);     // write-residency region
        stg256_el(out + base + off1, v1);
    } else {
        stg256_cs(out + base, v0);     // streaming write tail
        stg256_cs(out + base + off1, v1);
    }
}

// Tail kernel for any remainder (unused at this exact shape; kept for
// correctness on arbitrary out_size).
__global__ void stream_copy_tail(const float* __restrict__ in,
                                 float* __restrict__ out,
                                 size_t start, size_t n) {
    size_t i = start + blockIdx.x * (size_t)blockDim.x + threadIdx.x;
    if (i < n) out[i] = __ldcs(in + i);
}

extern "C" void kernel_launch(void* const* d_in, const int* in_sizes, int n_in,
                              void* d_out, int out_size) {
    const float* X = (const float*)d_in[0];
    float* out = (float*)d_out;

    size_t n = (size_t)out_size;                 // 35,651,584 floats
    size_t full_blocks = n / FLOATS_PER_BLOCK;   // 8704 exact here

    if (full_blocks > 0) {
        stream_copy_kernel<<<(unsigned)full_blocks, THREADS>>>(X, out);
    }
    size_t done = full_blocks * FLOATS_PER_BLOCK;
    if (done < n) {
        size_t rem = n - done;
        unsigned tb = (unsigned)((rem + 255) / 256);
        stream_copy_tail<<<tb, 256>>>(X, out, done, n);
    }
}